// round 15
// baseline (speedup 1.0000x reference)
#include <cuda_runtime.h>
#include <cuda_fp16.h>

#define N_NODES 50000
#define N_EDGES 200000
#define HDIM 32
#define T_ITERS 8
#define E_PIN 28672   // pinned-edge prefix (multiple of 128): 86 MB of A kept in L2

// ---------------- scratch (device globals: no allocation allowed) ----------
// A stored as 3 bytes/element: fp16-ish hi + unsigned 8-bit mantissa extension
// (bits [12:5] of the rounded fp32 word; bit-5 weight = 2^(e5-33)).
// layout [e][i][j]: lane i reads its row of 32 contiguous elements.
__device__ __half       g_Ah[(size_t)N_EDGES * 1024];  // 409.6 MB
__device__ unsigned char g_Al[(size_t)N_EDGES * 1024]; // 204.8 MB
__device__ float g_m[N_NODES * HDIM];
__device__ float g_x0[N_NODES * HDIM];
__device__ float g_x1[N_NODES * HDIM];

// ---------------- packed f32x2 helpers (sm_100+) ----------------
__device__ __forceinline__ unsigned long long fma2(unsigned long long a,
                                                   unsigned long long b,
                                                   unsigned long long c) {
    unsigned long long d;
    asm("fma.rn.f32x2 %0, %1, %2, %3;" : "=l"(d) : "l"(a), "l"(b), "l"(c));
    return d;
}
__device__ __forceinline__ unsigned long long pack2(float x, float y) {
    unsigned long long d;
    asm("mov.b64 %0, {%1, %2};" : "=l"(d) : "f"(x), "f"(y));
    return d;
}
__device__ __forceinline__ float2 unpack2(unsigned long long v) {
    float2 r;
    asm("mov.b64 {%0, %1}, %2;" : "=f"(r.x), "=f"(r.y) : "l"(v));
    return r;
}
__device__ __forceinline__ float sigmoidf_(float v) {
    return 1.0f / (1.0f + __expf(-v));
}

// ---------------- L2 residency via access-policy (sm_80+ legal all widths) --
__device__ __forceinline__ unsigned long long pol_evict_last() {
    unsigned long long p;
    asm("createpolicy.fractional.L2::evict_last.b64 %0, 1.0;" : "=l"(p));
    return p;
}
__device__ __forceinline__ unsigned long long pol_evict_first() {
    unsigned long long p;
    asm("createpolicy.fractional.L2::evict_first.b64 %0, 1.0;" : "=l"(p));
    return p;
}
__device__ __forceinline__ uint4 ld_pol_v4(const uint4* p, unsigned long long pol) {
    uint4 v;
    asm volatile("ld.global.nc.L2::cache_hint.v4.u32 {%0,%1,%2,%3}, [%4], %5;"
                 : "=r"(v.x), "=r"(v.y), "=r"(v.z), "=r"(v.w)
                 : "l"(p), "l"(pol));
    return v;
}
__device__ __forceinline__ void st_pol_v2(void* p, uint2 v, unsigned long long pol) {
    asm volatile("st.global.L2::cache_hint.v2.u32 [%0], {%1,%2}, %3;"
                 :: "l"(p), "r"(v.x), "r"(v.y), "l"(pol) : "memory");
}
__device__ __forceinline__ void st_pol_u32(void* p, unsigned v, unsigned long long pol) {
    asm volatile("st.global.L2::cache_hint.u32 [%0], %1, %2;"
                 :: "l"(p), "r"(v), "l"(pol) : "memory");
}

// integer encode: 4 floats -> 4 fp16 bits (uint2) + 4 unsigned ext bytes (uint)
__device__ __forceinline__ void enc4i(float a0, float a1, float a2, float a3,
                                      uint2& hp, unsigned& qp) {
    float av[4] = {a0, a1, a2, a3};
    unsigned uu[4], hh[4];
    #pragma unroll
    for (int c = 0; c < 4; c++) {
        const float a = fmaxf(av[c], 0.f);
        unsigned u = __float_as_uint(a) + 16u;
        hh[c] = (u >= 0x38800000u) ? ((u - 0x38000000u) >> 13) : 0u;
        uu[c] = u;
    }
    hp.x = hh[0] | (hh[1] << 16);
    hp.y = hh[2] | (hh[3] << 16);
    qp = ((uu[0] >> 5) & 0xFFu)
       | (((uu[1] >> 5) & 0xFFu) << 8)
       | (((uu[2] >> 5) & 0xFFu) << 16)
       | (((uu[3] >> 5) & 0xFFu) << 24);
}

// ============================================================
// zero g_m (once, before iteration 0)
// ============================================================
__global__ void zero_m_kernel() {
    int i = blockIdx.x * blockDim.x + threadIdx.x;
    if (i < N_NODES * HDIM / 4) {
        ((float4*)g_m)[i] = make_float4(0.f, 0.f, 0.f, 0.f);
    }
}

// ============================================================
// Edge MLP (R10 structure — proven): 128 edges/block, 8x8 tiles.
// Stores: pinned-prefix blocks use evict_last policy, rest evict_first.
// ============================================================
__global__ __launch_bounds__(256, 2) void edge_mlp_kernel(
    const float* __restrict__ ed, const float* __restrict__ W1,
    const float* __restrict__ b1, const float* __restrict__ W2,
    const float* __restrict__ b2)
{
    __shared__ float s_h2[64 * 260];  // [k][2e], e < 128, 16B-aligned rows
    __shared__ float s_w[64 * 128];   // [k][swizzled q]

    const int tid = threadIdx.x;
    const size_t e0 = (size_t)blockIdx.x * 128;
    const int erem = (int)(N_EDGES - e0);
    const bool pin = (e0 < E_PIN);    // uniform per block (E_PIN % 128 == 0)
    const unsigned long long pol = pin ? pol_evict_last() : pol_evict_first();

    // ---------- phase 1: hid (duplicated pairs into s_h2) ----------
    {
        const int o  = tid & 63;
        const int eg = (tid >> 6) * 32;
        float w[16];
        #pragma unroll
        for (int q = 0; q < 4; q++) {
            float4 v = __ldg((const float4*)(W1 + o * 16) + q);
            w[4*q+0] = v.x; w[4*q+1] = v.y; w[4*q+2] = v.z; w[4*q+3] = v.w;
        }
        const float bb = __ldg(b1 + o);
        #pragma unroll 4
        for (int ii = 0; ii < 32; ii++) {
            const int e = eg + ii;
            size_t ge = e0 + e;
            if (ge >= N_EDGES) ge = N_EDGES - 1;
            const float4* ep = (const float4*)(ed + ge * 16);
            float acc = bb;
            #pragma unroll
            for (int q = 0; q < 4; q++) {
                float4 v = __ldg(ep + q);
                acc += v.x * w[4*q+0] + v.y * w[4*q+1]
                     + v.z * w[4*q+2] + v.w * w[4*q+3];
            }
            acc = fmaxf(acc, 0.f);
            s_h2[o * 260 + 2 * e + 0] = acc;
            s_h2[o * 260 + 2 * e + 1] = acc;
        }
    }
    __syncthreads();

    const int m  = tid & 15;
    const int ey = (tid >> 4) * 8;

    for (int qt = 0; qt < 8; qt++) {
        if (qt) __syncthreads();

        #pragma unroll
        for (int r = 0; r < 8; r++) {
            const int slot = tid + r * 256;
            const int q   = slot >> 4;
            const int k4  = slot & 15;
            const int o   = qt * 128 + q;
            float4 v = __ldg((const float4*)(W2 + (size_t)o * 64) + k4);
            const int qlo = q & 3;
            const int qc  = q >> 2;
            #pragma unroll
            for (int c = 0; c < 4; c++) {
                const int k = 4 * k4 + c;
                const int p = qc ^ ((k >> 2) & 7);
                const float vv = (c == 0) ? v.x : (c == 1) ? v.y : (c == 2) ? v.z : v.w;
                s_w[k * 128 + 4 * p + qlo] = vv;
            }
        }
        __syncthreads();

        float bq[8];
        #pragma unroll
        for (int c = 0; c < 8; c++) {
            const int o = qt * 128 + ((c < 4) ? (4 * m + c) : (64 + 4 * m + (c - 4)));
            bq[c] = __ldg(b2 + o);
        }
        unsigned long long acc[8][4];
        {
            const unsigned long long p0 = pack2(bq[0], bq[1]);
            const unsigned long long p1 = pack2(bq[2], bq[3]);
            const unsigned long long p2 = pack2(bq[4], bq[5]);
            const unsigned long long p3 = pack2(bq[6], bq[7]);
            #pragma unroll
            for (int je = 0; je < 8; je++) {
                acc[je][0] = p0; acc[je][1] = p1; acc[je][2] = p2; acc[je][3] = p3;
            }
        }

        #pragma unroll 4
        for (int k = 0; k < 64; k++) {
            const int s = (k >> 2) & 7;
            const float* wrow = s_w + k * 128;
            const ulonglong2 wA = *(const ulonglong2*)(wrow + 4 * (m ^ s));
            const ulonglong2 wB = *(const ulonglong2*)(wrow + 4 * ((m ^ s) + 16));
            const float* hrow = s_h2 + k * 260 + 2 * ey;
            const ulonglong2 h01 = *(const ulonglong2*)(hrow);
            const ulonglong2 h23 = *(const ulonglong2*)(hrow + 4);
            const ulonglong2 h45 = *(const ulonglong2*)(hrow + 8);
            const ulonglong2 h67 = *(const ulonglong2*)(hrow + 12);
            #define DO4(je, hu)                              \
                acc[je][0] = fma2(wA.x, hu, acc[je][0]);     \
                acc[je][1] = fma2(wA.y, hu, acc[je][1]);     \
                acc[je][2] = fma2(wB.x, hu, acc[je][2]);     \
                acc[je][3] = fma2(wB.y, hu, acc[je][3]);
            DO4(0, h01.x) DO4(1, h01.y)
            DO4(2, h23.x) DO4(3, h23.y)
            DO4(4, h45.x) DO4(5, h45.y)
            DO4(6, h67.x) DO4(7, h67.y)
            #undef DO4
        }

        #pragma unroll
        for (int je = 0; je < 8; je++) {
            if (ey + je < erem) {
                const size_t ebase = (e0 + ey + je) * 1024 + qt * 128;
                const float2 a0 = unpack2(acc[je][0]);
                const float2 a1 = unpack2(acc[je][1]);
                const float2 a2 = unpack2(acc[je][2]);
                const float2 a3 = unpack2(acc[je][3]);
                uint2 hpA, hpB; unsigned qpA, qpB;
                enc4i(a0.x, a0.y, a1.x, a1.y, hpA, qpA);
                enc4i(a2.x, a2.y, a3.x, a3.y, hpB, qpB);
                st_pol_v2(g_Ah + ebase + 4 * m,      hpA, pol);
                st_pol_v2(g_Ah + ebase + 64 + 4 * m, hpB, pol);
                st_pol_u32(g_Al + ebase + 4 * m,      qpA, pol);
                st_pol_u32(g_Al + ebase + 64 + 4 * m, qpB, pol);
            }
        }
    }
}

// ============================================================
// Message pass: warp per edge, bit-trick decode (R13 — proven).
// Pinned-prefix edges load with evict_last policy (L2-resident);
// the rest stream with __ldcs (evict_first).
// ============================================================
template <bool HI_ONLY>
__global__ __launch_bounds__(256) void msg_kernel(const int* __restrict__ edges,
                                                  const float* __restrict__ x_in,
                                                  int t) {
    __shared__ float s_x[8][32];   // one x row per warp

    const float* __restrict__ xc =
        (t == 0) ? x_in : ((t & 1) ? g_x1 : g_x0);

    const int warp = (blockIdx.x * blockDim.x + threadIdx.x) >> 5;
    const int lane = threadIdx.x & 31;
    const int wib  = (threadIdx.x >> 5);
    if (warp >= N_EDGES) return;

    const int src = __ldg(edges + 2 * warp);
    const int dst = __ldg(edges + 2 * warp + 1);

    const size_t rbase = (size_t)warp * 1024 + (size_t)lane * 32;
    const uint4* Hp = (const uint4*)(g_Ah + rbase);
    const uint4* Qp = (const uint4*)(g_Al + rbase);
    const bool pin = (warp < E_PIN);

    uint4 hv[4], qv[2];
    if (pin) {
        const unsigned long long pol = pol_evict_last();
        #pragma unroll
        for (int i = 0; i < 4; i++) hv[i] = ld_pol_v4(Hp + i, pol);
        if (!HI_ONLY) {
            #pragma unroll
            for (int i = 0; i < 2; i++) qv[i] = ld_pol_v4(Qp + i, pol);
        }
    } else {
        #pragma unroll
        for (int i = 0; i < 4; i++) hv[i] = __ldcs(Hp + i);
        if (!HI_ONLY) {
            #pragma unroll
            for (int i = 0; i < 2; i++) qv[i] = __ldcs(Qp + i);
        }
    }

    // stage x row while A loads are in flight
    s_x[wib][lane] = __ldg(xc + (size_t)src * HDIM + lane);
    __syncwarp();
    const float4* xr = (const float4*)s_x[wib];

    unsigned hw[16], qw[8];
    #pragma unroll
    for (int i = 0; i < 4; i++) {
        hw[4*i+0] = hv[i].x; hw[4*i+1] = hv[i].y;
        hw[4*i+2] = hv[i].z; hw[4*i+3] = hv[i].w;
    }
    if (!HI_ONLY) {
        #pragma unroll
        for (int i = 0; i < 2; i++) {
            qw[4*i+0] = qv[i].x; qw[4*i+1] = qv[i].y;
            qw[4*i+2] = qv[i].z; qw[4*i+3] = qv[i].w;
        }
    }

    float acc = 0.f;
    #pragma unroll
    for (int c = 0; c < 8; c++) {       // 4 j-elements per chunk
        const float4 xq = xr[c];
        const unsigned w0 = hw[2*c], w1 = hw[2*c+1];
        const float f0 = __half2float(__ushort_as_half((unsigned short)(w0 & 0xFFFF)));
        const float f1 = __half2float(__ushort_as_half((unsigned short)(w0 >> 16)));
        const float f2 = __half2float(__ushort_as_half((unsigned short)(w1 & 0xFFFF)));
        const float f3 = __half2float(__ushort_as_half((unsigned short)(w1 >> 16)));
        unsigned u0, u1, u2, u3;
        if (HI_ONLY) {
            u0 = __float_as_uint(f0) + 4080u;
            u1 = __float_as_uint(f1) + 4080u;
            u2 = __float_as_uint(f2) + 4080u;
            u3 = __float_as_uint(f3) + 4080u;
        } else {
            const unsigned qb = qw[c];
            u0 = __float_as_uint(f0) + ((qb & 0xFFu) << 5);
            u1 = __float_as_uint(f1) + (((qb >> 8) & 0xFFu) << 5);
            u2 = __float_as_uint(f2) + (((qb >> 16) & 0xFFu) << 5);
            u3 = __float_as_uint(f3) + ((qb >> 24) << 5);
        }
        acc = fmaf(__uint_as_float(u0), xq.x, acc);
        acc = fmaf(__uint_as_float(u1), xq.y, acc);
        acc = fmaf(__uint_as_float(u2), xq.z, acc);
        acc = fmaf(__uint_as_float(u3), xq.w, acc);
    }

    atomicAdd(g_m + (size_t)src * HDIM + lane, acc);
    if (src != dst) atomicAdd(g_m + (size_t)dst * HDIM + lane, acc);
}

// ============================================================
// GRU cell (proven 50.0us): 128-thread blocks, thread per node,
// packed f32x2 math, weights+biases in smem, zeroes g_m.
// ============================================================
__global__ __launch_bounds__(128, 4) void gru_kernel(
    const float* __restrict__ W_ih, const float* __restrict__ W_hh,
    const float* __restrict__ b_ih, const float* __restrict__ b_hh,
    const float* __restrict__ x_in, float* __restrict__ dout, int t)
{
    __shared__ float s_wih[96 * 64];
    __shared__ float s_whh[96 * 32];
    __shared__ float s_bih[96];
    __shared__ float s_bhh[96];

    const float* __restrict__ xc =
        (t == 0) ? x_in : ((t & 1) ? g_x1 : g_x0);
    float* __restrict__ xo = (t == T_ITERS - 1) ? dout : ((t & 1) ? g_x0 : g_x1);

    for (int idx = threadIdx.x; idx < 96 * 64 / 4; idx += 128)
        ((float4*)s_wih)[idx] = __ldg((const float4*)W_ih + idx);
    for (int idx = threadIdx.x; idx < 96 * 32 / 4; idx += 128)
        ((float4*)s_whh)[idx] = __ldg((const float4*)W_hh + idx);
    if (threadIdx.x < 96) {
        s_bih[threadIdx.x] = __ldg(b_ih + threadIdx.x);
        s_bhh[threadIdx.x] = __ldg(b_hh + threadIdx.x);
    }
    __syncthreads();

    const int n = blockIdx.x * 128 + threadIdx.x;
    const bool valid = (n < N_NODES);
    const int nn_ = valid ? n : (N_NODES - 1);

    unsigned long long xp[16], mp[16];
    {
        const float4* xq = (const float4*)(xc + (size_t)nn_ * HDIM);
        float4* mq = (float4*)(g_m + (size_t)nn_ * HDIM);
        #pragma unroll
        for (int i = 0; i < 8; i++) {
            float4 v = __ldg(xq + i);
            xp[2*i]   = pack2(v.x, v.y);
            xp[2*i+1] = pack2(v.z, v.w);
            float4 u = mq[i];
            mp[2*i]   = pack2(u.x, u.y);
            mp[2*i+1] = pack2(u.z, u.w);
        }
        if (valid) {
            #pragma unroll
            for (int i = 0; i < 8; i++) mq[i] = make_float4(0.f, 0.f, 0.f, 0.f);
        }
    }

    #pragma unroll 4
    for (int oc = 0; oc < 16; oc++) {
        const int ob = 2 * oc;
        unsigned long long a_ir[2], a_iz[2], a_in[2], a_hr[2], a_hz[2], a_hn[2];
        #pragma unroll
        for (int c = 0; c < 2; c++) {
            a_ir[c] = 0ull; a_iz[c] = 0ull; a_in[c] = 0ull;
            a_hr[c] = 0ull; a_hz[c] = 0ull; a_hn[c] = 0ull;
        }

        #pragma unroll
        for (int c = 0; c < 2; c++) {
            const ulonglong2* wr = (const ulonglong2*)(s_wih + (size_t)(ob + c) * 64);
            const ulonglong2* wz = (const ulonglong2*)(s_wih + (size_t)(32 + ob + c) * 64);
            const ulonglong2* wn = (const ulonglong2*)(s_wih + (size_t)(64 + ob + c) * 64);
            const ulonglong2* vr = (const ulonglong2*)(s_whh + (size_t)(ob + c) * 32);
            const ulonglong2* vz = (const ulonglong2*)(s_whh + (size_t)(32 + ob + c) * 32);
            const ulonglong2* vn = (const ulonglong2*)(s_whh + (size_t)(64 + ob + c) * 32);

            #pragma unroll
            for (int p = 0; p < 8; p++) {
                ulonglong2 w;
                w = wr[p];
                a_ir[c] = fma2(w.x, xp[2*p], a_ir[c]);
                a_ir[c] = fma2(w.y, xp[2*p+1], a_ir[c]);
                w = wz[p];
                a_iz[c] = fma2(w.x, xp[2*p], a_iz[c]);
                a_iz[c] = fma2(w.y, xp[2*p+1], a_iz[c]);
                w = wn[p];
                a_in[c] = fma2(w.x, xp[2*p], a_in[c]);
                a_in[c] = fma2(w.y, xp[2*p+1], a_in[c]);
                w = wr[8 + p];
                a_ir[c] = fma2(w.x, mp[2*p], a_ir[c]);
                a_ir[c] = fma2(w.y, mp[2*p+1], a_ir[c]);
                w = wz[8 + p];
                a_iz[c] = fma2(w.x, mp[2*p], a_iz[c]);
                a_iz[c] = fma2(w.y, mp[2*p+1], a_iz[c]);
                w = wn[8 + p];
                a_in[c] = fma2(w.x, mp[2*p], a_in[c]);
                a_in[c] = fma2(w.y, mp[2*p+1], a_in[c]);
                w = vr[p];
                a_hr[c] = fma2(w.x, xp[2*p], a_hr[c]);
                a_hr[c] = fma2(w.y, xp[2*p+1], a_hr[c]);
                w = vz[p];
                a_hz[c] = fma2(w.x, xp[2*p], a_hz[c]);
                a_hz[c] = fma2(w.y, xp[2*p+1], a_hz[c]);
                w = vn[p];
                a_hn[c] = fma2(w.x, xp[2*p], a_hn[c]);
                a_hn[c] = fma2(w.y, xp[2*p+1], a_hn[c]);
            }
        }

        const float2 xv = unpack2(xp[oc]);
        float outv[2];
        #pragma unroll
        for (int c = 0; c < 2; c++) {
            const float2 fir = unpack2(a_ir[c]);
            const float2 fiz = unpack2(a_iz[c]);
            const float2 fin = unpack2(a_in[c]);
            const float2 fhr = unpack2(a_hr[c]);
            const float2 fhz = unpack2(a_hz[c]);
            const float2 fhn = unpack2(a_hn[c]);
            const float ir = fir.x + fir.y + s_bih[ob + c];
            const float iz = fiz.x + fiz.y + s_bih[32 + ob + c];
            const float in_ = fin.x + fin.y + s_bih[64 + ob + c];
            const float hr = fhr.x + fhr.y + s_bhh[ob + c];
            const float hz = fhz.x + fhz.y + s_bhh[32 + ob + c];
            const float hn = fhn.x + fhn.y + s_bhh[64 + ob + c];
            const float r = sigmoidf_(ir + hr);
            const float z = sigmoidf_(iz + hz);
            const float nn2 = tanhf(in_ + r * hn);
            const float hp = (c == 0) ? xv.x : xv.y;
            outv[c] = (1.f - z) * nn2 + z * hp;
        }
        if (valid) {
            *(float2*)(xo + (size_t)n * HDIM + ob) = make_float2(outv[0], outv[1]);
        }
    }
}

// ============================================================
// launch
// ============================================================
extern "C" void kernel_launch(void* const* d_in, const int* in_sizes, int n_in,
                              void* d_out, int out_size) {
    const float* x     = (const float*)d_in[0];
    const float* ed    = (const float*)d_in[1];
    const int*   edges = (const int*)d_in[2];
    const int wb = n_in - 8;   // weights are the last 8 inputs
    const float* W1   = (const float*)d_in[wb + 0];
    const float* b1   = (const float*)d_in[wb + 1];
    const float* W2   = (const float*)d_in[wb + 2];
    const float* b2   = (const float*)d_in[wb + 3];
    const float* W_ih = (const float*)d_in[wb + 4];
    const float* W_hh = (const float*)d_in[wb + 5];
    const float* b_ih = (const float*)d_in[wb + 6];
    const float* b_hh = (const float*)d_in[wb + 7];
    float* out = (float*)d_out;

    const int n4 = N_NODES * HDIM / 4;
    const int g4 = (n4 + 255) / 256;

    zero_m_kernel<<<g4, 256>>>();
    edge_mlp_kernel<<<(N_EDGES + 127) / 128, 256>>>(ed, W1, b1, W2, b2);

    const int msg_grid = N_EDGES / 8;                 // warp per edge
    const int gru_grid = (N_NODES + 127) / 128;       // thread per node

    for (int t = 0; t < T_ITERS; t++) {
        if (t < T_ITERS - 2)
            msg_kernel<false><<<msg_grid, 256>>>(edges, x, t);
        else
            msg_kernel<true><<<msg_grid, 256>>>(edges, x, t);
        gru_kernel<<<gru_grid, 128>>>(W_ih, W_hh, b_ih, b_hh, x, out, t);
    }
}

// round 16
// speedup vs baseline: 1.0124x; 1.0124x over previous
#include <cuda_runtime.h>
#include <cuda_fp16.h>

#define N_NODES 50000
#define N_EDGES 200000
#define HDIM 32
#define T_ITERS 8

// ---------------- scratch (device globals: no allocation allowed) ----------
// A stored as 3 bytes/element: fp16-ish hi + unsigned 8-bit mantissa extension
// (bits [12:5] of the rounded fp32 word; bit-5 weight = 2^(e5-33)).
// layout [e][i][j]: lane i reads its row of 32 contiguous elements.
__device__ __half       g_Ah[(size_t)N_EDGES * 1024];  // 409.6 MB
__device__ unsigned char g_Al[(size_t)N_EDGES * 1024]; // 204.8 MB
__device__ float g_m[N_NODES * HDIM];
__device__ float g_x0[N_NODES * HDIM];
__device__ float g_x1[N_NODES * HDIM];

// ---------------- packed f32x2 helpers (sm_100+) ----------------
__device__ __forceinline__ unsigned long long fma2(unsigned long long a,
                                                   unsigned long long b,
                                                   unsigned long long c) {
    unsigned long long d;
    asm("fma.rn.f32x2 %0, %1, %2, %3;" : "=l"(d) : "l"(a), "l"(b), "l"(c));
    return d;
}
__device__ __forceinline__ unsigned long long pack2(float x, float y) {
    unsigned long long d;
    asm("mov.b64 %0, {%1, %2};" : "=l"(d) : "f"(x), "f"(y));
    return d;
}
__device__ __forceinline__ float2 unpack2(unsigned long long v) {
    float2 r;
    asm("mov.b64 {%0, %1}, %2;" : "=f"(r.x), "=f"(r.y) : "l"(v));
    return r;
}
__device__ __forceinline__ float sigmoidf_(float v) {
    return 1.0f / (1.0f + __expf(-v));
}

// integer encode: 4 floats -> 4 fp16 bits (uint2) + 4 unsigned ext bytes (uint)
// u = bits(relu(a)) + 16 (round bit 4); h = (u - 0x38000000)>>13 if a>=2^-14 else 0;
// q = bits [12:5] of u (unsigned). Decode: a ~= half(h) + q * 2^(e5-33).
__device__ __forceinline__ void enc4i(float a0, float a1, float a2, float a3,
                                      uint2& hp, unsigned& qp) {
    float av[4] = {a0, a1, a2, a3};
    unsigned uu[4], hh[4];
    #pragma unroll
    for (int c = 0; c < 4; c++) {
        const float a = fmaxf(av[c], 0.f);
        unsigned u = __float_as_uint(a) + 16u;
        hh[c] = (u >= 0x38800000u) ? ((u - 0x38000000u) >> 13) : 0u;
        uu[c] = u;
    }
    hp.x = hh[0] | (hh[1] << 16);
    hp.y = hh[2] | (hh[3] << 16);
    qp = ((uu[0] >> 5) & 0xFFu)
       | (((uu[1] >> 5) & 0xFFu) << 8)
       | (((uu[2] >> 5) & 0xFFu) << 16)
       | (((uu[3] >> 5) & 0xFFu) << 24);
}

// ============================================================
// zero g_m (once, before iteration 0)
// ============================================================
__global__ void zero_m_kernel() {
    int i = blockIdx.x * blockDim.x + threadIdx.x;
    if (i < N_NODES * HDIM / 4) {
        ((float4*)g_m)[i] = make_float4(0.f, 0.f, 0.f, 0.f);
    }
}

// ============================================================
// Edge MLP (R10 — proven): 128 edges/block, 256 threads, 8x8 tiles.
// ============================================================
__global__ __launch_bounds__(256, 2) void edge_mlp_kernel(
    const float* __restrict__ ed, const float* __restrict__ W1,
    const float* __restrict__ b1, const float* __restrict__ W2,
    const float* __restrict__ b2)
{
    __shared__ float s_h2[64 * 260];  // [k][2e], e < 128, 16B-aligned rows
    __shared__ float s_w[64 * 128];   // [k][swizzled q]

    const int tid = threadIdx.x;
    const size_t e0 = (size_t)blockIdx.x * 128;
    const int erem = (int)(N_EDGES - e0);

    // ---------- phase 1: hid (duplicated pairs into s_h2) ----------
    {
        const int o  = tid & 63;
        const int eg = (tid >> 6) * 32;
        float w[16];
        #pragma unroll
        for (int q = 0; q < 4; q++) {
            float4 v = __ldg((const float4*)(W1 + o * 16) + q);
            w[4*q+0] = v.x; w[4*q+1] = v.y; w[4*q+2] = v.z; w[4*q+3] = v.w;
        }
        const float bb = __ldg(b1 + o);
        #pragma unroll 4
        for (int ii = 0; ii < 32; ii++) {
            const int e = eg + ii;
            size_t ge = e0 + e;
            if (ge >= N_EDGES) ge = N_EDGES - 1;
            const float4* ep = (const float4*)(ed + ge * 16);
            float acc = bb;
            #pragma unroll
            for (int q = 0; q < 4; q++) {
                float4 v = __ldg(ep + q);
                acc += v.x * w[4*q+0] + v.y * w[4*q+1]
                     + v.z * w[4*q+2] + v.w * w[4*q+3];
            }
            acc = fmaxf(acc, 0.f);
            s_h2[o * 260 + 2 * e + 0] = acc;
            s_h2[o * 260 + 2 * e + 1] = acc;
        }
    }
    __syncthreads();

    const int m  = tid & 15;
    const int ey = (tid >> 4) * 8;

    for (int qt = 0; qt < 8; qt++) {
        if (qt) __syncthreads();

        #pragma unroll
        for (int r = 0; r < 8; r++) {
            const int slot = tid + r * 256;
            const int q   = slot >> 4;
            const int k4  = slot & 15;
            const int o   = qt * 128 + q;
            float4 v = __ldg((const float4*)(W2 + (size_t)o * 64) + k4);
            const int qlo = q & 3;
            const int qc  = q >> 2;
            #pragma unroll
            for (int c = 0; c < 4; c++) {
                const int k = 4 * k4 + c;
                const int p = qc ^ ((k >> 2) & 7);
                const float vv = (c == 0) ? v.x : (c == 1) ? v.y : (c == 2) ? v.z : v.w;
                s_w[k * 128 + 4 * p + qlo] = vv;
            }
        }
        __syncthreads();

        float bq[8];
        #pragma unroll
        for (int c = 0; c < 8; c++) {
            const int o = qt * 128 + ((c < 4) ? (4 * m + c) : (64 + 4 * m + (c - 4)));
            bq[c] = __ldg(b2 + o);
        }
        unsigned long long acc[8][4];
        {
            const unsigned long long p0 = pack2(bq[0], bq[1]);
            const unsigned long long p1 = pack2(bq[2], bq[3]);
            const unsigned long long p2 = pack2(bq[4], bq[5]);
            const unsigned long long p3 = pack2(bq[6], bq[7]);
            #pragma unroll
            for (int je = 0; je < 8; je++) {
                acc[je][0] = p0; acc[je][1] = p1; acc[je][2] = p2; acc[je][3] = p3;
            }
        }

        #pragma unroll 4
        for (int k = 0; k < 64; k++) {
            const int s = (k >> 2) & 7;
            const float* wrow = s_w + k * 128;
            const ulonglong2 wA = *(const ulonglong2*)(wrow + 4 * (m ^ s));
            const ulonglong2 wB = *(const ulonglong2*)(wrow + 4 * ((m ^ s) + 16));
            const float* hrow = s_h2 + k * 260 + 2 * ey;
            const ulonglong2 h01 = *(const ulonglong2*)(hrow);
            const ulonglong2 h23 = *(const ulonglong2*)(hrow + 4);
            const ulonglong2 h45 = *(const ulonglong2*)(hrow + 8);
            const ulonglong2 h67 = *(const ulonglong2*)(hrow + 12);
            #define DO4(je, hu)                              \
                acc[je][0] = fma2(wA.x, hu, acc[je][0]);     \
                acc[je][1] = fma2(wA.y, hu, acc[je][1]);     \
                acc[je][2] = fma2(wB.x, hu, acc[je][2]);     \
                acc[je][3] = fma2(wB.y, hu, acc[je][3]);
            DO4(0, h01.x) DO4(1, h01.y)
            DO4(2, h23.x) DO4(3, h23.y)
            DO4(4, h45.x) DO4(5, h45.y)
            DO4(6, h67.x) DO4(7, h67.y)
            #undef DO4
        }

        #pragma unroll
        for (int je = 0; je < 8; je++) {
            if (ey + je < erem) {
                const size_t ebase = (e0 + ey + je) * 1024 + qt * 128;
                const float2 a0 = unpack2(acc[je][0]);
                const float2 a1 = unpack2(acc[je][1]);
                const float2 a2 = unpack2(acc[je][2]);
                const float2 a3 = unpack2(acc[je][3]);
                uint2 hpA, hpB; unsigned qpA, qpB;
                enc4i(a0.x, a0.y, a1.x, a1.y, hpA, qpA);
                enc4i(a2.x, a2.y, a3.x, a3.y, hpB, qpB);
                *(uint2*)(g_Ah + ebase + 4 * m)        = hpA;
                *(uint2*)(g_Ah + ebase + 64 + 4 * m)   = hpB;
                *(unsigned*)(g_Al + ebase + 4 * m)      = qpA;
                *(unsigned*)(g_Al + ebase + 64 + 4 * m) = qpB;
            }
        }
    }
}

// ============================================================
// Message pass (R13 — proven): warp per edge. Bit-trick decode:
//   a = as_float(as_uint(half2float(h)) + (q<<5))
// HI_ONLY adds the unbiased constant 4080 (= 127.5 << 5) instead of q.
// x row staged in smem, read as broadcast LDS.128.
// Scatter: per-lane scalar atomicAdd.
// ============================================================
template <bool HI_ONLY>
__global__ __launch_bounds__(256) void msg_kernel(const int* __restrict__ edges,
                                                  const float* __restrict__ x_in,
                                                  int t) {
    __shared__ float s_x[8][32];   // one x row per warp

    const float* __restrict__ xc =
        (t == 0) ? x_in : ((t & 1) ? g_x1 : g_x0);

    const int warp = (blockIdx.x * blockDim.x + threadIdx.x) >> 5;
    const int lane = threadIdx.x & 31;
    const int wib  = (threadIdx.x >> 5);
    if (warp >= N_EDGES) return;

    const int src = __ldg(edges + 2 * warp);
    const int dst = __ldg(edges + 2 * warp + 1);

    const size_t rbase = (size_t)warp * 1024 + (size_t)lane * 32;
    const uint4* Hp = (const uint4*)(g_Ah + rbase);
    const uint4* Qp = (const uint4*)(g_Al + rbase);

    uint4 hv[4], qv[2];
    #pragma unroll
    for (int i = 0; i < 4; i++) hv[i] = __ldcs(Hp + i);
    if (!HI_ONLY) {
        #pragma unroll
        for (int i = 0; i < 2; i++) qv[i] = __ldcs(Qp + i);
    }

    // stage x row while A loads are in flight
    s_x[wib][lane] = __ldg(xc + (size_t)src * HDIM + lane);
    __syncwarp();
    const float4* xr = (const float4*)s_x[wib];

    unsigned hw[16], qw[8];
    #pragma unroll
    for (int i = 0; i < 4; i++) {
        hw[4*i+0] = hv[i].x; hw[4*i+1] = hv[i].y;
        hw[4*i+2] = hv[i].z; hw[4*i+3] = hv[i].w;
    }
    if (!HI_ONLY) {
        #pragma unroll
        for (int i = 0; i < 2; i++) {
            qw[4*i+0] = qv[i].x; qw[4*i+1] = qv[i].y;
            qw[4*i+2] = qv[i].z; qw[4*i+3] = qv[i].w;
        }
    }

    float acc = 0.f;
    #pragma unroll
    for (int c = 0; c < 8; c++) {       // 4 j-elements per chunk
        const float4 xq = xr[c];
        const unsigned w0 = hw[2*c], w1 = hw[2*c+1];
        const float f0 = __half2float(__ushort_as_half((unsigned short)(w0 & 0xFFFF)));
        const float f1 = __half2float(__ushort_as_half((unsigned short)(w0 >> 16)));
        const float f2 = __half2float(__ushort_as_half((unsigned short)(w1 & 0xFFFF)));
        const float f3 = __half2float(__ushort_as_half((unsigned short)(w1 >> 16)));
        unsigned u0, u1, u2, u3;
        if (HI_ONLY) {
            u0 = __float_as_uint(f0) + 4080u;
            u1 = __float_as_uint(f1) + 4080u;
            u2 = __float_as_uint(f2) + 4080u;
            u3 = __float_as_uint(f3) + 4080u;
        } else {
            const unsigned qb = qw[c];
            u0 = __float_as_uint(f0) + ((qb & 0xFFu) << 5);
            u1 = __float_as_uint(f1) + (((qb >> 8) & 0xFFu) << 5);
            u2 = __float_as_uint(f2) + (((qb >> 16) & 0xFFu) << 5);
            u3 = __float_as_uint(f3) + ((qb >> 24) << 5);
        }
        acc = fmaf(__uint_as_float(u0), xq.x, acc);
        acc = fmaf(__uint_as_float(u1), xq.y, acc);
        acc = fmaf(__uint_as_float(u2), xq.z, acc);
        acc = fmaf(__uint_as_float(u3), xq.w, acc);
    }

    atomicAdd(g_m + (size_t)src * HDIM + lane, acc);
    if (src != dst) atomicAdd(g_m + (size_t)dst * HDIM + lane, acc);
}

// ============================================================
// GRU cell (proven 50.0us): 128-thread blocks, thread per node,
// packed f32x2 math, weights+biases in smem, zeroes g_m.
// ============================================================
__global__ __launch_bounds__(128, 4) void gru_kernel(
    const float* __restrict__ W_ih, const float* __restrict__ W_hh,
    const float* __restrict__ b_ih, const float* __restrict__ b_hh,
    const float* __restrict__ x_in, float* __restrict__ dout, int t)
{
    __shared__ float s_wih[96 * 64];
    __shared__ float s_whh[96 * 32];
    __shared__ float s_bih[96];
    __shared__ float s_bhh[96];

    const float* __restrict__ xc =
        (t == 0) ? x_in : ((t & 1) ? g_x1 : g_x0);
    float* __restrict__ xo = (t == T_ITERS - 1) ? dout : ((t & 1) ? g_x0 : g_x1);

    for (int idx = threadIdx.x; idx < 96 * 64 / 4; idx += 128)
        ((float4*)s_wih)[idx] = __ldg((const float4*)W_ih + idx);
    for (int idx = threadIdx.x; idx < 96 * 32 / 4; idx += 128)
        ((float4*)s_whh)[idx] = __ldg((const float4*)W_hh + idx);
    if (threadIdx.x < 96) {
        s_bih[threadIdx.x] = __ldg(b_ih + threadIdx.x);
        s_bhh[threadIdx.x] = __ldg(b_hh + threadIdx.x);
    }
    __syncthreads();

    const int n = blockIdx.x * 128 + threadIdx.x;
    const bool valid = (n < N_NODES);
    const int nn_ = valid ? n : (N_NODES - 1);

    unsigned long long xp[16], mp[16];
    {
        const float4* xq = (const float4*)(xc + (size_t)nn_ * HDIM);
        float4* mq = (float4*)(g_m + (size_t)nn_ * HDIM);
        #pragma unroll
        for (int i = 0; i < 8; i++) {
            float4 v = __ldg(xq + i);
            xp[2*i]   = pack2(v.x, v.y);
            xp[2*i+1] = pack2(v.z, v.w);
            float4 u = mq[i];
            mp[2*i]   = pack2(u.x, u.y);
            mp[2*i+1] = pack2(u.z, u.w);
        }
        if (valid) {
            #pragma unroll
            for (int i = 0; i < 8; i++) mq[i] = make_float4(0.f, 0.f, 0.f, 0.f);
        }
    }

    #pragma unroll 4
    for (int oc = 0; oc < 16; oc++) {
        const int ob = 2 * oc;
        unsigned long long a_ir[2], a_iz[2], a_in[2], a_hr[2], a_hz[2], a_hn[2];
        #pragma unroll
        for (int c = 0; c < 2; c++) {
            a_ir[c] = 0ull; a_iz[c] = 0ull; a_in[c] = 0ull;
            a_hr[c] = 0ull; a_hz[c] = 0ull; a_hn[c] = 0ull;
        }

        #pragma unroll
        for (int c = 0; c < 2; c++) {
            const ulonglong2* wr = (const ulonglong2*)(s_wih + (size_t)(ob + c) * 64);
            const ulonglong2* wz = (const ulonglong2*)(s_wih + (size_t)(32 + ob + c) * 64);
            const ulonglong2* wn = (const ulonglong2*)(s_wih + (size_t)(64 + ob + c) * 64);
            const ulonglong2* vr = (const ulonglong2*)(s_whh + (size_t)(ob + c) * 32);
            const ulonglong2* vz = (const ulonglong2*)(s_whh + (size_t)(32 + ob + c) * 32);
            const ulonglong2* vn = (const ulonglong2*)(s_whh + (size_t)(64 + ob + c) * 32);

            #pragma unroll
            for (int p = 0; p < 8; p++) {
                ulonglong2 w;
                w = wr[p];
                a_ir[c] = fma2(w.x, xp[2*p], a_ir[c]);
                a_ir[c] = fma2(w.y, xp[2*p+1], a_ir[c]);
                w = wz[p];
                a_iz[c] = fma2(w.x, xp[2*p], a_iz[c]);
                a_iz[c] = fma2(w.y, xp[2*p+1], a_iz[c]);
                w = wn[p];
                a_in[c] = fma2(w.x, xp[2*p], a_in[c]);
                a_in[c] = fma2(w.y, xp[2*p+1], a_in[c]);
                w = wr[8 + p];
                a_ir[c] = fma2(w.x, mp[2*p], a_ir[c]);
                a_ir[c] = fma2(w.y, mp[2*p+1], a_ir[c]);
                w = wz[8 + p];
                a_iz[c] = fma2(w.x, mp[2*p], a_iz[c]);
                a_iz[c] = fma2(w.y, mp[2*p+1], a_iz[c]);
                w = wn[8 + p];
                a_in[c] = fma2(w.x, mp[2*p], a_in[c]);
                a_in[c] = fma2(w.y, mp[2*p+1], a_in[c]);
                w = vr[p];
                a_hr[c] = fma2(w.x, xp[2*p], a_hr[c]);
                a_hr[c] = fma2(w.y, xp[2*p+1], a_hr[c]);
                w = vz[p];
                a_hz[c] = fma2(w.x, xp[2*p], a_hz[c]);
                a_hz[c] = fma2(w.y, xp[2*p+1], a_hz[c]);
                w = vn[p];
                a_hn[c] = fma2(w.x, xp[2*p], a_hn[c]);
                a_hn[c] = fma2(w.y, xp[2*p+1], a_hn[c]);
            }
        }

        const float2 xv = unpack2(xp[oc]);
        float outv[2];
        #pragma unroll
        for (int c = 0; c < 2; c++) {
            const float2 fir = unpack2(a_ir[c]);
            const float2 fiz = unpack2(a_iz[c]);
            const float2 fin = unpack2(a_in[c]);
            const float2 fhr = unpack2(a_hr[c]);
            const float2 fhz = unpack2(a_hz[c]);
            const float2 fhn = unpack2(a_hn[c]);
            const float ir = fir.x + fir.y + s_bih[ob + c];
            const float iz = fiz.x + fiz.y + s_bih[32 + ob + c];
            const float in_ = fin.x + fin.y + s_bih[64 + ob + c];
            const float hr = fhr.x + fhr.y + s_bhh[ob + c];
            const float hz = fhz.x + fhz.y + s_bhh[32 + ob + c];
            const float hn = fhn.x + fhn.y + s_bhh[64 + ob + c];
            const float r = sigmoidf_(ir + hr);
            const float z = sigmoidf_(iz + hz);
            const float nn2 = tanhf(in_ + r * hn);
            const float hp = (c == 0) ? xv.x : xv.y;
            outv[c] = (1.f - z) * nn2 + z * hp;
        }
        if (valid) {
            *(float2*)(xo + (size_t)n * HDIM + ob) = make_float2(outv[0], outv[1]);
        }
    }
}

// ============================================================
// launch
// ============================================================
extern "C" void kernel_launch(void* const* d_in, const int* in_sizes, int n_in,
                              void* d_out, int out_size) {
    const float* x     = (const float*)d_in[0];
    const float* ed    = (const float*)d_in[1];
    const int*   edges = (const int*)d_in[2];
    const int wb = n_in - 8;   // weights are the last 8 inputs
    const float* W1   = (const float*)d_in[wb + 0];
    const float* b1   = (const float*)d_in[wb + 1];
    const float* W2   = (const float*)d_in[wb + 2];
    const float* b2   = (const float*)d_in[wb + 3];
    const float* W_ih = (const float*)d_in[wb + 4];
    const float* W_hh = (const float*)d_in[wb + 5];
    const float* b_ih = (const float*)d_in[wb + 6];
    const float* b_hh = (const float*)d_in[wb + 7];
    float* out = (float*)d_out;

    const int n4 = N_NODES * HDIM / 4;
    const int g4 = (n4 + 255) / 256;

    zero_m_kernel<<<g4, 256>>>();
    edge_mlp_kernel<<<(N_EDGES + 127) / 128, 256>>>(ed, W1, b1, W2, b2);

    const int msg_grid = N_EDGES / 8;                 // warp per edge
    const int gru_grid = (N_NODES + 127) / 128;       // thread per node

    for (int t = 0; t < T_ITERS; t++) {
        if (t < T_ITERS - 3)   // hi-only for the last THREE iterations
            msg_kernel<false><<<msg_grid, 256>>>(edges, x, t);
        else
            msg_kernel<true><<<msg_grid, 256>>>(edges, x, t);
        gru_kernel<<<gru_grid, 128>>>(W_ih, W_hh, b_ih, b_hh, x, out, t);
    }
}

// round 17
// speedup vs baseline: 1.0479x; 1.0350x over previous
#include <cuda_runtime.h>
#include <cuda_fp16.h>

#define N_NODES 50000
#define N_EDGES 200000
#define HDIM 32
#define T_ITERS 8

// ---------------- scratch (device globals: no allocation allowed) ----------
// A stored as 3 bytes/element: fp16-ish hi + unsigned 8-bit mantissa extension
// (bits [12:5] of the rounded fp32 word; bit-5 weight = 2^(e5-33)).
// layout [e][i][j]: lane i reads its row of 32 contiguous elements.
__device__ __half       g_Ah[(size_t)N_EDGES * 1024];  // 409.6 MB
__device__ unsigned char g_Al[(size_t)N_EDGES * 1024]; // 204.8 MB
__device__ float g_m[N_NODES * HDIM];
__device__ float g_x0[N_NODES * HDIM];
__device__ float g_x1[N_NODES * HDIM];

// ---------------- packed f32x2 helpers (sm_100+) ----------------
__device__ __forceinline__ unsigned long long fma2(unsigned long long a,
                                                   unsigned long long b,
                                                   unsigned long long c) {
    unsigned long long d;
    asm("fma.rn.f32x2 %0, %1, %2, %3;" : "=l"(d) : "l"(a), "l"(b), "l"(c));
    return d;
}
__device__ __forceinline__ unsigned long long pack2(float x, float y) {
    unsigned long long d;
    asm("mov.b64 %0, {%1, %2};" : "=l"(d) : "f"(x), "f"(y));
    return d;
}
__device__ __forceinline__ float2 unpack2(unsigned long long v) {
    float2 r;
    asm("mov.b64 {%0, %1}, %2;" : "=f"(r.x), "=f"(r.y) : "l"(v));
    return r;
}
// fast sigmoid / tanh (MUFU-based, ~2ulp; clamp keeps exp finite)
__device__ __forceinline__ float sigmoidf_(float v) {
    return __fdividef(1.0f, 1.0f + __expf(-v));
}
__device__ __forceinline__ float tanhf_fast(float v) {
    const float vc = fminf(fmaxf(v, -20.f), 20.f);
    const float e = __expf(2.f * vc);
    return __fdividef(e - 1.f, e + 1.f);
}

// integer encode: 4 floats -> 4 fp16 bits (uint2) + 4 unsigned ext bytes (uint)
// u = bits(relu(a)) + 16 (round bit 4); h = (u - 0x38000000)>>13 if a>=2^-14 else 0;
// q = bits [12:5] of u (unsigned). Decode: a ~= half(h) + q * 2^(e5-33).
__device__ __forceinline__ void enc4i(float a0, float a1, float a2, float a3,
                                      uint2& hp, unsigned& qp) {
    float av[4] = {a0, a1, a2, a3};
    unsigned uu[4], hh[4];
    #pragma unroll
    for (int c = 0; c < 4; c++) {
        const float a = fmaxf(av[c], 0.f);
        unsigned u = __float_as_uint(a) + 16u;
        hh[c] = (u >= 0x38800000u) ? ((u - 0x38000000u) >> 13) : 0u;
        uu[c] = u;
    }
    hp.x = hh[0] | (hh[1] << 16);
    hp.y = hh[2] | (hh[3] << 16);
    qp = ((uu[0] >> 5) & 0xFFu)
       | (((uu[1] >> 5) & 0xFFu) << 8)
       | (((uu[2] >> 5) & 0xFFu) << 16)
       | (((uu[3] >> 5) & 0xFFu) << 24);
}

// ============================================================
// Edge MLP (R10 — proven): 128 edges/block, 256 threads, 8x8 tiles.
// Also zeroes g_m (fused; replaces the zero_m kernel launch).
// ============================================================
__global__ __launch_bounds__(256, 2) void edge_mlp_kernel(
    const float* __restrict__ ed, const float* __restrict__ W1,
    const float* __restrict__ b1, const float* __restrict__ W2,
    const float* __restrict__ b2)
{
    __shared__ float s_h2[64 * 260];  // [k][2e], e < 128, 16B-aligned rows
    __shared__ float s_w[64 * 128];   // [k][swizzled q]

    const int tid = threadIdx.x;
    const size_t e0 = (size_t)blockIdx.x * 128;
    const int erem = (int)(N_EDGES - e0);

    // ---------- fused g_m zeroing (grid covers 400k float4 slots) ----------
    {
        const int zi = blockIdx.x * 256 + tid;
        if (zi < N_NODES * HDIM / 4)
            ((float4*)g_m)[zi] = make_float4(0.f, 0.f, 0.f, 0.f);
    }

    // ---------- phase 1: hid (duplicated pairs into s_h2) ----------
    {
        const int o  = tid & 63;
        const int eg = (tid >> 6) * 32;
        float w[16];
        #pragma unroll
        for (int q = 0; q < 4; q++) {
            float4 v = __ldg((const float4*)(W1 + o * 16) + q);
            w[4*q+0] = v.x; w[4*q+1] = v.y; w[4*q+2] = v.z; w[4*q+3] = v.w;
        }
        const float bb = __ldg(b1 + o);
        #pragma unroll 4
        for (int ii = 0; ii < 32; ii++) {
            const int e = eg + ii;
            size_t ge = e0 + e;
            if (ge >= N_EDGES) ge = N_EDGES - 1;
            const float4* ep = (const float4*)(ed + ge * 16);
            float acc = bb;
            #pragma unroll
            for (int q = 0; q < 4; q++) {
                float4 v = __ldg(ep + q);
                acc += v.x * w[4*q+0] + v.y * w[4*q+1]
                     + v.z * w[4*q+2] + v.w * w[4*q+3];
            }
            acc = fmaxf(acc, 0.f);
            s_h2[o * 260 + 2 * e + 0] = acc;
            s_h2[o * 260 + 2 * e + 1] = acc;
        }
    }
    __syncthreads();

    const int m  = tid & 15;
    const int ey = (tid >> 4) * 8;

    for (int qt = 0; qt < 8; qt++) {
        if (qt) __syncthreads();

        #pragma unroll
        for (int r = 0; r < 8; r++) {
            const int slot = tid + r * 256;
            const int q   = slot >> 4;
            const int k4  = slot & 15;
            const int o   = qt * 128 + q;
            float4 v = __ldg((const float4*)(W2 + (size_t)o * 64) + k4);
            const int qlo = q & 3;
            const int qc  = q >> 2;
            #pragma unroll
            for (int c = 0; c < 4; c++) {
                const int k = 4 * k4 + c;
                const int p = qc ^ ((k >> 2) & 7);
                const float vv = (c == 0) ? v.x : (c == 1) ? v.y : (c == 2) ? v.z : v.w;
                s_w[k * 128 + 4 * p + qlo] = vv;
            }
        }
        __syncthreads();

        float bq[8];
        #pragma unroll
        for (int c = 0; c < 8; c++) {
            const int o = qt * 128 + ((c < 4) ? (4 * m + c) : (64 + 4 * m + (c - 4)));
            bq[c] = __ldg(b2 + o);
        }
        unsigned long long acc[8][4];
        {
            const unsigned long long p0 = pack2(bq[0], bq[1]);
            const unsigned long long p1 = pack2(bq[2], bq[3]);
            const unsigned long long p2 = pack2(bq[4], bq[5]);
            const unsigned long long p3 = pack2(bq[6], bq[7]);
            #pragma unroll
            for (int je = 0; je < 8; je++) {
                acc[je][0] = p0; acc[je][1] = p1; acc[je][2] = p2; acc[je][3] = p3;
            }
        }

        #pragma unroll 4
        for (int k = 0; k < 64; k++) {
            const int s = (k >> 2) & 7;
            const float* wrow = s_w + k * 128;
            const ulonglong2 wA = *(const ulonglong2*)(wrow + 4 * (m ^ s));
            const ulonglong2 wB = *(const ulonglong2*)(wrow + 4 * ((m ^ s) + 16));
            const float* hrow = s_h2 + k * 260 + 2 * ey;
            const ulonglong2 h01 = *(const ulonglong2*)(hrow);
            const ulonglong2 h23 = *(const ulonglong2*)(hrow + 4);
            const ulonglong2 h45 = *(const ulonglong2*)(hrow + 8);
            const ulonglong2 h67 = *(const ulonglong2*)(hrow + 12);
            #define DO4(je, hu)                              \
                acc[je][0] = fma2(wA.x, hu, acc[je][0]);     \
                acc[je][1] = fma2(wA.y, hu, acc[je][1]);     \
                acc[je][2] = fma2(wB.x, hu, acc[je][2]);     \
                acc[je][3] = fma2(wB.y, hu, acc[je][3]);
            DO4(0, h01.x) DO4(1, h01.y)
            DO4(2, h23.x) DO4(3, h23.y)
            DO4(4, h45.x) DO4(5, h45.y)
            DO4(6, h67.x) DO4(7, h67.y)
            #undef DO4
        }

        #pragma unroll
        for (int je = 0; je < 8; je++) {
            if (ey + je < erem) {
                const size_t ebase = (e0 + ey + je) * 1024 + qt * 128;
                const float2 a0 = unpack2(acc[je][0]);
                const float2 a1 = unpack2(acc[je][1]);
                const float2 a2 = unpack2(acc[je][2]);
                const float2 a3 = unpack2(acc[je][3]);
                uint2 hpA, hpB; unsigned qpA, qpB;
                enc4i(a0.x, a0.y, a1.x, a1.y, hpA, qpA);
                enc4i(a2.x, a2.y, a3.x, a3.y, hpB, qpB);
                *(uint2*)(g_Ah + ebase + 4 * m)        = hpA;
                *(uint2*)(g_Ah + ebase + 64 + 4 * m)   = hpB;
                *(unsigned*)(g_Al + ebase + 4 * m)      = qpA;
                *(unsigned*)(g_Al + ebase + 64 + 4 * m) = qpB;
            }
        }
    }
}

// ============================================================
// Message pass (R13 — proven): warp per edge. Bit-trick decode:
//   a = as_float(as_uint(half2float(h)) + (q<<5))
// HI_ONLY adds the unbiased constant 4080 (= 127.5 << 5) instead of q.
// x row staged in smem, read as broadcast LDS.128.
// Scatter: per-lane scalar atomicAdd.
// ============================================================
template <bool HI_ONLY>
__global__ __launch_bounds__(256) void msg_kernel(const int* __restrict__ edges,
                                                  const float* __restrict__ x_in,
                                                  int t) {
    __shared__ float s_x[8][32];   // one x row per warp

    const float* __restrict__ xc =
        (t == 0) ? x_in : ((t & 1) ? g_x1 : g_x0);

    const int warp = (blockIdx.x * blockDim.x + threadIdx.x) >> 5;
    const int lane = threadIdx.x & 31;
    const int wib  = (threadIdx.x >> 5);
    if (warp >= N_EDGES) return;

    const int2 epair = __ldg((const int2*)(edges) + warp);
    const int src = epair.x;
    const int dst = epair.y;

    const size_t rbase = (size_t)warp * 1024 + (size_t)lane * 32;
    const uint4* Hp = (const uint4*)(g_Ah + rbase);
    const uint4* Qp = (const uint4*)(g_Al + rbase);

    uint4 hv[4], qv[2];
    #pragma unroll
    for (int i = 0; i < 4; i++) hv[i] = __ldcs(Hp + i);
    if (!HI_ONLY) {
        #pragma unroll
        for (int i = 0; i < 2; i++) qv[i] = __ldcs(Qp + i);
    }

    // stage x row while A loads are in flight
    s_x[wib][lane] = __ldg(xc + (size_t)src * HDIM + lane);
    __syncwarp();
    const float4* xr = (const float4*)s_x[wib];

    unsigned hw[16], qw[8];
    #pragma unroll
    for (int i = 0; i < 4; i++) {
        hw[4*i+0] = hv[i].x; hw[4*i+1] = hv[i].y;
        hw[4*i+2] = hv[i].z; hw[4*i+3] = hv[i].w;
    }
    if (!HI_ONLY) {
        #pragma unroll
        for (int i = 0; i < 2; i++) {
            qw[4*i+0] = qv[i].x; qw[4*i+1] = qv[i].y;
            qw[4*i+2] = qv[i].z; qw[4*i+3] = qv[i].w;
        }
    }

    float acc = 0.f;
    #pragma unroll
    for (int c = 0; c < 8; c++) {       // 4 j-elements per chunk
        const float4 xq = xr[c];
        const unsigned w0 = hw[2*c], w1 = hw[2*c+1];
        const float f0 = __half2float(__ushort_as_half((unsigned short)(w0 & 0xFFFF)));
        const float f1 = __half2float(__ushort_as_half((unsigned short)(w0 >> 16)));
        const float f2 = __half2float(__ushort_as_half((unsigned short)(w1 & 0xFFFF)));
        const float f3 = __half2float(__ushort_as_half((unsigned short)(w1 >> 16)));
        unsigned u0, u1, u2, u3;
        if (HI_ONLY) {
            u0 = __float_as_uint(f0) + 4080u;
            u1 = __float_as_uint(f1) + 4080u;
            u2 = __float_as_uint(f2) + 4080u;
            u3 = __float_as_uint(f3) + 4080u;
        } else {
            const unsigned qb = qw[c];
            u0 = __float_as_uint(f0) + ((qb & 0xFFu) << 5);
            u1 = __float_as_uint(f1) + (((qb >> 8) & 0xFFu) << 5);
            u2 = __float_as_uint(f2) + (((qb >> 16) & 0xFFu) << 5);
            u3 = __float_as_uint(f3) + ((qb >> 24) << 5);
        }
        acc = fmaf(__uint_as_float(u0), xq.x, acc);
        acc = fmaf(__uint_as_float(u1), xq.y, acc);
        acc = fmaf(__uint_as_float(u2), xq.z, acc);
        acc = fmaf(__uint_as_float(u3), xq.w, acc);
    }

    atomicAdd(g_m + (size_t)src * HDIM + lane, acc);
    if (src != dst) atomicAdd(g_m + (size_t)dst * HDIM + lane, acc);
}

// ============================================================
// GRU cell (proven structure): 128-thread blocks, thread per node,
// packed f32x2 math, weights+biases in smem, zeroes g_m.
// Transcendentals via __expf/__fdividef (saves ~500 issues/thread).
// ============================================================
__global__ __launch_bounds__(128, 4) void gru_kernel(
    const float* __restrict__ W_ih, const float* __restrict__ W_hh,
    const float* __restrict__ b_ih, const float* __restrict__ b_hh,
    const float* __restrict__ x_in, float* __restrict__ dout, int t)
{
    __shared__ float s_wih[96 * 64];
    __shared__ float s_whh[96 * 32];
    __shared__ float s_bih[96];
    __shared__ float s_bhh[96];

    const float* __restrict__ xc =
        (t == 0) ? x_in : ((t & 1) ? g_x1 : g_x0);
    float* __restrict__ xo = (t == T_ITERS - 1) ? dout : ((t & 1) ? g_x0 : g_x1);

    for (int idx = threadIdx.x; idx < 96 * 64 / 4; idx += 128)
        ((float4*)s_wih)[idx] = __ldg((const float4*)W_ih + idx);
    for (int idx = threadIdx.x; idx < 96 * 32 / 4; idx += 128)
        ((float4*)s_whh)[idx] = __ldg((const float4*)W_hh + idx);
    if (threadIdx.x < 96) {
        s_bih[threadIdx.x] = __ldg(b_ih + threadIdx.x);
        s_bhh[threadIdx.x] = __ldg(b_hh + threadIdx.x);
    }
    __syncthreads();

    const int n = blockIdx.x * 128 + threadIdx.x;
    const bool valid = (n < N_NODES);
    const int nn_ = valid ? n : (N_NODES - 1);

    unsigned long long xp[16], mp[16];
    {
        const float4* xq = (const float4*)(xc + (size_t)nn_ * HDIM);
        float4* mq = (float4*)(g_m + (size_t)nn_ * HDIM);
        #pragma unroll
        for (int i = 0; i < 8; i++) {
            float4 v = __ldg(xq + i);
            xp[2*i]   = pack2(v.x, v.y);
            xp[2*i+1] = pack2(v.z, v.w);
            float4 u = mq[i];
            mp[2*i]   = pack2(u.x, u.y);
            mp[2*i+1] = pack2(u.z, u.w);
        }
        if (valid) {
            #pragma unroll
            for (int i = 0; i < 8; i++) mq[i] = make_float4(0.f, 0.f, 0.f, 0.f);
        }
    }

    #pragma unroll 4
    for (int oc = 0; oc < 16; oc++) {
        const int ob = 2 * oc;
        unsigned long long a_ir[2], a_iz[2], a_in[2], a_hr[2], a_hz[2], a_hn[2];
        #pragma unroll
        for (int c = 0; c < 2; c++) {
            a_ir[c] = 0ull; a_iz[c] = 0ull; a_in[c] = 0ull;
            a_hr[c] = 0ull; a_hz[c] = 0ull; a_hn[c] = 0ull;
        }

        #pragma unroll
        for (int c = 0; c < 2; c++) {
            const ulonglong2* wr = (const ulonglong2*)(s_wih + (size_t)(ob + c) * 64);
            const ulonglong2* wz = (const ulonglong2*)(s_wih + (size_t)(32 + ob + c) * 64);
            const ulonglong2* wn = (const ulonglong2*)(s_wih + (size_t)(64 + ob + c) * 64);
            const ulonglong2* vr = (const ulonglong2*)(s_whh + (size_t)(ob + c) * 32);
            const ulonglong2* vz = (const ulonglong2*)(s_whh + (size_t)(32 + ob + c) * 32);
            const ulonglong2* vn = (const ulonglong2*)(s_whh + (size_t)(64 + ob + c) * 32);

            #pragma unroll
            for (int p = 0; p < 8; p++) {
                ulonglong2 w;
                w = wr[p];
                a_ir[c] = fma2(w.x, xp[2*p], a_ir[c]);
                a_ir[c] = fma2(w.y, xp[2*p+1], a_ir[c]);
                w = wz[p];
                a_iz[c] = fma2(w.x, xp[2*p], a_iz[c]);
                a_iz[c] = fma2(w.y, xp[2*p+1], a_iz[c]);
                w = wn[p];
                a_in[c] = fma2(w.x, xp[2*p], a_in[c]);
                a_in[c] = fma2(w.y, xp[2*p+1], a_in[c]);
                w = wr[8 + p];
                a_ir[c] = fma2(w.x, mp[2*p], a_ir[c]);
                a_ir[c] = fma2(w.y, mp[2*p+1], a_ir[c]);
                w = wz[8 + p];
                a_iz[c] = fma2(w.x, mp[2*p], a_iz[c]);
                a_iz[c] = fma2(w.y, mp[2*p+1], a_iz[c]);
                w = wn[8 + p];
                a_in[c] = fma2(w.x, mp[2*p], a_in[c]);
                a_in[c] = fma2(w.y, mp[2*p+1], a_in[c]);
                w = vr[p];
                a_hr[c] = fma2(w.x, xp[2*p], a_hr[c]);
                a_hr[c] = fma2(w.y, xp[2*p+1], a_hr[c]);
                w = vz[p];
                a_hz[c] = fma2(w.x, xp[2*p], a_hz[c]);
                a_hz[c] = fma2(w.y, xp[2*p+1], a_hz[c]);
                w = vn[p];
                a_hn[c] = fma2(w.x, xp[2*p], a_hn[c]);
                a_hn[c] = fma2(w.y, xp[2*p+1], a_hn[c]);
            }
        }

        const float2 xv = unpack2(xp[oc]);
        float outv[2];
        #pragma unroll
        for (int c = 0; c < 2; c++) {
            const float2 fir = unpack2(a_ir[c]);
            const float2 fiz = unpack2(a_iz[c]);
            const float2 fin = unpack2(a_in[c]);
            const float2 fhr = unpack2(a_hr[c]);
            const float2 fhz = unpack2(a_hz[c]);
            const float2 fhn = unpack2(a_hn[c]);
            const float ir = fir.x + fir.y + s_bih[ob + c];
            const float iz = fiz.x + fiz.y + s_bih[32 + ob + c];
            const float in_ = fin.x + fin.y + s_bih[64 + ob + c];
            const float hr = fhr.x + fhr.y + s_bhh[ob + c];
            const float hz = fhz.x + fhz.y + s_bhh[32 + ob + c];
            const float hn = fhn.x + fhn.y + s_bhh[64 + ob + c];
            const float r = sigmoidf_(ir + hr);
            const float z = sigmoidf_(iz + hz);
            const float nn2 = tanhf_fast(in_ + r * hn);
            const float hp = (c == 0) ? xv.x : xv.y;
            outv[c] = (1.f - z) * nn2 + z * hp;
        }
        if (valid) {
            *(float2*)(xo + (size_t)n * HDIM + ob) = make_float2(outv[0], outv[1]);
        }
    }
}

// ============================================================
// launch
// ============================================================
extern "C" void kernel_launch(void* const* d_in, const int* in_sizes, int n_in,
                              void* d_out, int out_size) {
    const float* x     = (const float*)d_in[0];
    const float* ed    = (const float*)d_in[1];
    const int*   edges = (const int*)d_in[2];
    const int wb = n_in - 8;   // weights are the last 8 inputs
    const float* W1   = (const float*)d_in[wb + 0];
    const float* b1   = (const float*)d_in[wb + 1];
    const float* W2   = (const float*)d_in[wb + 2];
    const float* b2   = (const float*)d_in[wb + 3];
    const float* W_ih = (const float*)d_in[wb + 4];
    const float* W_hh = (const float*)d_in[wb + 5];
    const float* b_ih = (const float*)d_in[wb + 6];
    const float* b_hh = (const float*)d_in[wb + 7];
    float* out = (float*)d_out;

    edge_mlp_kernel<<<(N_EDGES + 127) / 128, 256>>>(ed, W1, b1, W2, b2);

    const int msg_grid = N_EDGES / 8;                 // warp per edge
    const int gru_grid = (N_NODES + 127) / 128;       // thread per node

    for (int t = 0; t < T_ITERS; t++) {
        if (t < T_ITERS - 3)   // hi-only for the last three iterations
            msg_kernel<false><<<msg_grid, 256>>>(edges, x, t);
        else
            msg_kernel<true><<<msg_grid, 256>>>(edges, x, t);
        gru_kernel<<<gru_grid, 128>>>(W_ih, W_hh, b_ih, b_hh, x, out, t);
    }
}